// round 4
// baseline (speedup 1.0000x reference)
#include <cuda_runtime.h>
#include <cuda_bf16.h>
#include <cstdint>

// Problem constants
#define N_ROWS   8192      // 2 * B * S^3
#define C_DIM    16
#define NB_K     32        // partial slots per row (one per 256-row tile)
#define ESCALE   14.4269504088896340f   // 10 * log2(e): logits/T in log2 domain

// Scratch (device globals: no allocation allowed)
__device__ float g_mm[N_ROWS * C_DIM];       // pooled+flattened [8192][16]
__device__ float g_fu[N_ROWS * C_DIM];       // normalized features
__device__ float g_fs[N_ROWS * C_DIM];       // normalized * ESCALE
__device__ float g_all[N_ROWS * NB_K];       // per-row partial exp-sums, row-major
__device__ float g_blocksum[32];             // per-block loss partials

// ---------------------------------------------------------------------------
// Kernel 1: AdaptiveAvgPool3d(64->8) for both tensors, write [8192][16] fp32.
// ---------------------------------------------------------------------------
__global__ void __launch_bounds__(256) pool_kernel(const float* __restrict__ p1,
                                                   const float* __restrict__ p2)
{
    int bid = blockIdx.x;            // 0..2047
    int t   = bid >> 10;             // tensor select
    int r   = bid & 1023;
    int b   = r >> 7;
    int c   = (r >> 3) & 15;
    int sd  = r & 7;

    const float* p = t ? p2 : p1;
    int tid    = threadIdx.x;
    int sh     = tid >> 5;           // warp id == sy
    int lane   = tid & 31;
    int rowsel = lane >> 4;
    int wid4   = lane & 15;

    const float4* base = (const float4*)(p + ((((b << 4) + c) * 64 + (sd << 3)) << 12)
                                           + (sh << 3) * 64);

    float acc = 0.f;
#pragma unroll
    for (int dz = 0; dz < 8; dz++) {
#pragma unroll
        for (int hp = 0; hp < 4; hp++) {
            float4 v = base[dz * 1024 + (hp * 2 + rowsel) * 16 + wid4];
            acc += (v.x + v.y) + (v.z + v.w);
        }
    }
    acc += __shfl_xor_sync(0xffffffffu, acc, 1);
    acc += __shfl_xor_sync(0xffffffffu, acc, 16);

    if (((lane & 1) == 0) && lane < 16) {
        int sx  = lane >> 1;
        int row = t * 4096 + b * 512 + sd * 64 + sh * 8 + sx;
        g_mm[row * C_DIM + c] = acc * (1.0f / 512.0f);
    }
}

// ---------------------------------------------------------------------------
// Kernel 2: project_head (Linear->ReLU->Linear) + F.normalize per row.
// ---------------------------------------------------------------------------
__global__ void __launch_bounds__(256) mlp_kernel(const float* __restrict__ w1,
                                                  const float* __restrict__ b1,
                                                  const float* __restrict__ w2,
                                                  const float* __restrict__ b2)
{
    __shared__ float sw1[256], sw2[256], sb1[16], sb2[16];
    int tid = threadIdx.x;
    sw1[tid] = w1[tid];
    sw2[tid] = w2[tid];
    if (tid < 16) { sb1[tid] = b1[tid]; sb2[tid] = b2[tid]; }
    __syncthreads();

    int row = blockIdx.x * 256 + tid;

    float x[16];
    const float4* mm4 = (const float4*)(g_mm + row * C_DIM);
#pragma unroll
    for (int q = 0; q < 4; q++) {
        float4 v = mm4[q];
        x[q * 4 + 0] = v.x; x[q * 4 + 1] = v.y; x[q * 4 + 2] = v.z; x[q * 4 + 3] = v.w;
    }

    float h[16];
#pragma unroll
    for (int k = 0; k < 16; k++) {
        float s = sb1[k];
#pragma unroll
        for (int cc = 0; cc < 16; cc++) s = fmaf(sw1[k * 16 + cc], x[cc], s);
        h[k] = fmaxf(s, 0.f);
    }

    float f[16];
    float nsq = 0.f;
#pragma unroll
    for (int k = 0; k < 16; k++) {
        float s = sb2[k];
#pragma unroll
        for (int cc = 0; cc < 16; cc++) s = fmaf(sw2[k * 16 + cc], h[cc], s);
        f[k] = s;
        nsq = fmaf(s, s, nsq);
    }
    float inv = 1.0f / fmaxf(sqrtf(nsq), 1e-12f);

    float4* fu4 = (float4*)(g_fu + row * C_DIM);
    float4* fs4 = (float4*)(g_fs + row * C_DIM);
#pragma unroll
    for (int q = 0; q < 4; q++) {
        float4 u;
        u.x = f[q * 4 + 0] * inv; u.y = f[q * 4 + 1] * inv;
        u.z = f[q * 4 + 2] * inv; u.w = f[q * 4 + 3] * inv;
        fu4[q] = u;
        float4 s2;
        s2.x = u.x * ESCALE; s2.y = u.y * ESCALE; s2.z = u.z * ESCALE; s2.w = u.w * ESCALE;
        fs4[q] = s2;
    }
}

// ---------------------------------------------------------------------------
// Packed f32x2 helpers
// ---------------------------------------------------------------------------
__device__ __forceinline__ unsigned long long fma2(unsigned long long a,
                                                   unsigned long long b,
                                                   unsigned long long c)
{
    unsigned long long d;
    asm("fma.rn.f32x2 %0, %1, %2, %3;" : "=l"(d) : "l"(a), "l"(b), "l"(c));
    return d;
}
__device__ __forceinline__ unsigned long long mul2(unsigned long long a,
                                                   unsigned long long b)
{
    unsigned long long d;
    asm("mul.rn.f32x2 %0, %1, %2;" : "=l"(d) : "l"(a), "l"(b));
    return d;
}
__device__ __forceinline__ float sum2(unsigned long long a)
{
    float lo, hi;
    asm("mov.b64 {%0, %1}, %2;" : "=f"(lo), "=f"(hi) : "l"(a));
    return lo + hi;
}
__device__ __forceinline__ float ex2_approx(float x)
{
    float r;
    asm("ex2.approx.f32 %0, %1;" : "=f"(r) : "f"(x));
    return r;
}

// ---------------------------------------------------------------------------
// Kernel 3: symmetric partial exp-sums of the NxN similarity matrix.
// Grid (32, 32) x 128 threads; blocks with jb < ib exit immediately.
//   - Upper blocks (ib < jb): compute the 256x256 tile once; each exp feeds
//     both the i-row sum (register) and the j-row sum (warp-butterfly ->
//     per-warp shared colsum). Row sums -> g_all[i][jb], col sums -> g_all[j][ib].
//   - Diagonal blocks (ib == jb): full tile minus diagonal, row sums only.
// Every g_all[row][k] slot is written exactly once -> race-free, deterministic.
// ---------------------------------------------------------------------------
__global__ void __launch_bounds__(128) logits_kernel()
{
    __shared__ ulonglong2 sj[128 * 4];   // 128 j-rows * 16 floats = 8 KB
    __shared__ float csw[4 * 128];       // per-warp column partial sums, 2 KB

    int ib = blockIdx.x;
    int jb = blockIdx.y;
    if (jb < ib) return;
    bool diag = (ib == jb);

    int tid  = threadIdx.x;
    int w    = tid >> 5;
    int lane = tid & 31;

    int i0 = ib * 256 + tid;
    int i1 = i0 + 128;

    ulonglong2 A0[4], A1[4];
    const ulonglong2* fs = (const ulonglong2*)g_fs;
#pragma unroll
    for (int q = 0; q < 4; q++) { A0[q] = fs[i0 * 4 + q]; A1[q] = fs[i1 * 4 + q]; }

    const ulonglong2* fu = (const ulonglong2*)g_fu;
    float sum0 = 0.f, sum1 = 0.f;
    int jch = jb * 256;

    for (int tph = 0; tph < 2; tph++) {
        int j0 = jch + tph * 128;
        __syncthreads();   // protects sj and csw reuse across phases
#pragma unroll
        for (int q = 0; q < 4; q++) sj[tid * 4 + q] = fu[(j0 + tid) * 4 + q];
        if (!diag) {
#pragma unroll
            for (int s = 0; s < 4; s++) csw[w * 128 + s * 32 + lane] = 0.f;
        }
        __syncthreads();

        if (!diag) {
#pragma unroll 2
            for (int jj = 0; jj < 128; jj++) {
                ulonglong2 B0 = sj[jj * 4 + 0];
                ulonglong2 B1 = sj[jj * 4 + 1];
                ulonglong2 B2 = sj[jj * 4 + 2];
                ulonglong2 B3 = sj[jj * 4 + 3];

                unsigned long long acc0 = mul2(A0[0].x, B0.x);
                acc0 = fma2(A0[0].y, B0.y, acc0);
                acc0 = fma2(A0[1].x, B1.x, acc0);
                acc0 = fma2(A0[1].y, B1.y, acc0);
                acc0 = fma2(A0[2].x, B2.x, acc0);
                acc0 = fma2(A0[2].y, B2.y, acc0);
                acc0 = fma2(A0[3].x, B3.x, acc0);
                acc0 = fma2(A0[3].y, B3.y, acc0);

                unsigned long long acc1 = mul2(A1[0].x, B0.x);
                acc1 = fma2(A1[0].y, B0.y, acc1);
                acc1 = fma2(A1[1].x, B1.x, acc1);
                acc1 = fma2(A1[1].y, B1.y, acc1);
                acc1 = fma2(A1[2].x, B2.x, acc1);
                acc1 = fma2(A1[2].y, B2.y, acc1);
                acc1 = fma2(A1[3].x, B3.x, acc1);
                acc1 = fma2(A1[3].y, B3.y, acc1);

                float e0 = ex2_approx(sum2(acc0));
                float e1 = ex2_approx(sum2(acc1));
                sum0 += e0;
                sum1 += e1;

                // column contribution: reduce e0+e1 across the warp
                float c = e0 + e1;
                c += __shfl_xor_sync(0xffffffffu, c, 16);
                c += __shfl_xor_sync(0xffffffffu, c, 8);
                c += __shfl_xor_sync(0xffffffffu, c, 4);
                c += __shfl_xor_sync(0xffffffffu, c, 2);
                c += __shfl_xor_sync(0xffffffffu, c, 1);
                if (lane == 0) csw[w * 128 + jj] += c;
            }

            __syncthreads();
            // 128 threads: one j each; sum 4 warps' partials, write slot [j][ib]
            float ctot = csw[0 * 128 + tid] + csw[1 * 128 + tid]
                       + csw[2 * 128 + tid] + csw[3 * 128 + tid];
            g_all[(j0 + tid) * NB_K + ib] = ctot;
        } else {
#pragma unroll 2
            for (int jj = 0; jj < 128; jj++) {
                ulonglong2 B0 = sj[jj * 4 + 0];
                ulonglong2 B1 = sj[jj * 4 + 1];
                ulonglong2 B2 = sj[jj * 4 + 2];
                ulonglong2 B3 = sj[jj * 4 + 3];

                unsigned long long acc0 = mul2(A0[0].x, B0.x);
                acc0 = fma2(A0[0].y, B0.y, acc0);
                acc0 = fma2(A0[1].x, B1.x, acc0);
                acc0 = fma2(A0[1].y, B1.y, acc0);
                acc0 = fma2(A0[2].x, B2.x, acc0);
                acc0 = fma2(A0[2].y, B2.y, acc0);
                acc0 = fma2(A0[3].x, B3.x, acc0);
                acc0 = fma2(A0[3].y, B3.y, acc0);

                unsigned long long acc1 = mul2(A1[0].x, B0.x);
                acc1 = fma2(A1[0].y, B0.y, acc1);
                acc1 = fma2(A1[1].x, B1.x, acc1);
                acc1 = fma2(A1[1].y, B1.y, acc1);
                acc1 = fma2(A1[2].x, B2.x, acc1);
                acc1 = fma2(A1[2].y, B2.y, acc1);
                acc1 = fma2(A1[3].x, B3.x, acc1);
                acc1 = fma2(A1[3].y, B3.y, acc1);

                float e0 = ex2_approx(sum2(acc0));
                float e1 = ex2_approx(sum2(acc1));
                int jg = j0 + jj;
                if (jg != i0) sum0 += e0;
                if (jg != i1) sum1 += e1;
            }
        }
    }

    g_all[i0 * NB_K + jb] = sum0;
    g_all[i1 * NB_K + jb] = sum1;
}

// ---------------------------------------------------------------------------
// Kernel 4a: per-row lse - pos, reduced within each of 32 blocks.
// g_all is row-major: each thread reads 128 contiguous bytes.
// ---------------------------------------------------------------------------
__global__ void __launch_bounds__(256) final_partial_kernel()
{
    __shared__ float red[256];
    int tid = threadIdx.x;
    int i   = blockIdx.x * 256 + tid;    // exactly 8192 threads, one row each

    const float4* pr = (const float4*)(g_all + i * NB_K);
    float S = 0.f;
#pragma unroll
    for (int q = 0; q < 8; q++) {
        float4 v = pr[q];
        S += (v.x + v.y) + (v.z + v.w);
    }

    int p = (i + 4096) & (N_ROWS - 1);
    const float4* a  = (const float4*)(g_fu + i * C_DIM);
    const float4* bb = (const float4*)(g_fu + p * C_DIM);
    float dot = 0.f;
#pragma unroll
    for (int q = 0; q < 4; q++) {
        float4 av = a[q], bv = bb[q];
        dot = fmaf(av.x, bv.x, dot);
        dot = fmaf(av.y, bv.y, dot);
        dot = fmaf(av.z, bv.z, dot);
        dot = fmaf(av.w, bv.w, dot);
    }

    red[tid] = logf(S) - 10.0f * dot;
    __syncthreads();
#pragma unroll
    for (int s = 128; s > 0; s >>= 1) {
        if (tid < s) red[tid] += red[tid + s];
        __syncthreads();
    }
    if (tid == 0) g_blocksum[blockIdx.x] = red[0];
}

// ---------------------------------------------------------------------------
// Kernel 4b: combine 32 block sums -> mean.
// ---------------------------------------------------------------------------
__global__ void __launch_bounds__(32) final_combine_kernel(float* __restrict__ out)
{
    int lane = threadIdx.x;
    float v = g_blocksum[lane];
#pragma unroll
    for (int s = 16; s > 0; s >>= 1) v += __shfl_xor_sync(0xffffffffu, v, s);
    if (lane == 0) out[0] = v * (1.0f / (float)N_ROWS);
}

// ---------------------------------------------------------------------------
extern "C" void kernel_launch(void* const* d_in, const int* in_sizes, int n_in,
                              void* d_out, int out_size)
{
    const float* p1 = (const float*)d_in[0];
    const float* p2 = (const float*)d_in[1];
    const float* w1 = (const float*)d_in[2];
    const float* b1 = (const float*)d_in[3];
    const float* w2 = (const float*)d_in[4];
    const float* b2 = (const float*)d_in[5];

    pool_kernel<<<2048, 256>>>(p1, p2);
    mlp_kernel<<<32, 256>>>(w1, b1, w2, b2);
    logits_kernel<<<dim3(32, 32), 128>>>();
    final_partial_kernel<<<32, 256>>>();
    final_combine_kernel<<<1, 32>>>((float*)d_out);
}

// round 5
// speedup vs baseline: 1.0576x; 1.0576x over previous
#include <cuda_runtime.h>
#include <cuda_bf16.h>
#include <cstdint>

// Problem constants
#define N_ROWS   8192      // 2 * B * S^3
#define C_DIM    16
#define NB_J     32        // j-chunks for logits kernel (chunk = 256 rows)
#define ESCALE   14.4269504088896340f   // 10 * log2(e): logits/T in log2 domain

// Scratch (device globals: no allocation allowed)
__device__ float g_mmA[N_ROWS * C_DIM];      // pool partial (dz 0..3), raw sums
__device__ float g_mmB[N_ROWS * C_DIM];      // pool partial (dz 4..7), raw sums
__device__ float g_fu[N_ROWS * C_DIM];       // normalized features
__device__ float g_fs[N_ROWS * C_DIM];       // normalized * ESCALE
__device__ float g_partial[NB_J * N_ROWS];   // partial exp-sums per j-chunk
__device__ float g_blocksum[32];             // per-block loss partials

// ---------------------------------------------------------------------------
// Kernel 1: AdaptiveAvgPool3d(64->8), split over dz halves for 2x occupancy.
// Grid: 4096 blocks (tensor, b, c, sd, half), 256 threads (8 warps = 8 sy).
// Each block accumulates 4 of the 8 dz planes into its own buffer half.
// ---------------------------------------------------------------------------
__global__ void __launch_bounds__(256) pool_kernel(const float* __restrict__ p1,
                                                   const float* __restrict__ p2)
{
    int bid  = blockIdx.x;           // 0..4095
    int t    = bid >> 11;            // tensor select
    int r    = bid & 2047;
    int b    = r >> 8;
    int c    = (r >> 4) & 15;
    int sd   = (r >> 1) & 7;
    int half = r & 1;

    const float* p = t ? p2 : p1;
    int tid    = threadIdx.x;
    int sh     = tid >> 5;           // warp id == sy
    int lane   = tid & 31;
    int rowsel = lane >> 4;
    int wid4   = lane & 15;

    const float4* base = (const float4*)(p + ((((b << 4) + c) * 64 + (sd << 3) + (half << 2)) << 12)
                                           + (sh << 3) * 64);

    float acc = 0.f;
#pragma unroll
    for (int dz = 0; dz < 4; dz++) {
#pragma unroll
        for (int hp = 0; hp < 4; hp++) {
            float4 v = base[dz * 1024 + (hp * 2 + rowsel) * 16 + wid4];
            acc += (v.x + v.y) + (v.z + v.w);
        }
    }
    acc += __shfl_xor_sync(0xffffffffu, acc, 1);
    acc += __shfl_xor_sync(0xffffffffu, acc, 16);

    if (((lane & 1) == 0) && lane < 16) {
        int sx  = lane >> 1;
        int row = t * 4096 + b * 512 + sd * 64 + sh * 8 + sx;
        float* dst = half ? g_mmB : g_mmA;
        dst[row * C_DIM + c] = acc;
    }
}

// ---------------------------------------------------------------------------
// Kernel 2: combine pool halves + project_head + F.normalize per row.
// ---------------------------------------------------------------------------
__global__ void __launch_bounds__(256) mlp_kernel(const float* __restrict__ w1,
                                                  const float* __restrict__ b1,
                                                  const float* __restrict__ w2,
                                                  const float* __restrict__ b2)
{
    __shared__ float sw1[256], sw2[256], sb1[16], sb2[16];
    int tid = threadIdx.x;
    sw1[tid] = w1[tid];
    sw2[tid] = w2[tid];
    if (tid < 16) { sb1[tid] = b1[tid]; sb2[tid] = b2[tid]; }
    __syncthreads();

    int row = blockIdx.x * 256 + tid;

    float x[16];
    const float4* ma4 = (const float4*)(g_mmA + row * C_DIM);
    const float4* mb4 = (const float4*)(g_mmB + row * C_DIM);
#pragma unroll
    for (int q = 0; q < 4; q++) {
        float4 va = ma4[q], vb = mb4[q];
        x[q * 4 + 0] = (va.x + vb.x) * (1.0f / 512.0f);
        x[q * 4 + 1] = (va.y + vb.y) * (1.0f / 512.0f);
        x[q * 4 + 2] = (va.z + vb.z) * (1.0f / 512.0f);
        x[q * 4 + 3] = (va.w + vb.w) * (1.0f / 512.0f);
    }

    float h[16];
#pragma unroll
    for (int k = 0; k < 16; k++) {
        float s = sb1[k];
#pragma unroll
        for (int cc = 0; cc < 16; cc++) s = fmaf(sw1[k * 16 + cc], x[cc], s);
        h[k] = fmaxf(s, 0.f);
    }

    float f[16];
    float nsq = 0.f;
#pragma unroll
    for (int k = 0; k < 16; k++) {
        float s = sb2[k];
#pragma unroll
        for (int cc = 0; cc < 16; cc++) s = fmaf(sw2[k * 16 + cc], h[cc], s);
        f[k] = s;
        nsq = fmaf(s, s, nsq);
    }
    float inv = 1.0f / fmaxf(sqrtf(nsq), 1e-12f);

    float4* fu4 = (float4*)(g_fu + row * C_DIM);
    float4* fs4 = (float4*)(g_fs + row * C_DIM);
#pragma unroll
    for (int q = 0; q < 4; q++) {
        float4 u;
        u.x = f[q * 4 + 0] * inv; u.y = f[q * 4 + 1] * inv;
        u.z = f[q * 4 + 2] * inv; u.w = f[q * 4 + 3] * inv;
        fu4[q] = u;
        float4 s2;
        s2.x = u.x * ESCALE; s2.y = u.y * ESCALE; s2.z = u.z * ESCALE; s2.w = u.w * ESCALE;
        fs4[q] = s2;
    }
}

// ---------------------------------------------------------------------------
// Packed f32x2 helpers
// ---------------------------------------------------------------------------
__device__ __forceinline__ unsigned long long fma2(unsigned long long a,
                                                   unsigned long long b,
                                                   unsigned long long c)
{
    unsigned long long d;
    asm("fma.rn.f32x2 %0, %1, %2, %3;" : "=l"(d) : "l"(a), "l"(b), "l"(c));
    return d;
}
__device__ __forceinline__ unsigned long long mul2(unsigned long long a,
                                                   unsigned long long b)
{
    unsigned long long d;
    asm("mul.rn.f32x2 %0, %1, %2;" : "=l"(d) : "l"(a), "l"(b));
    return d;
}
__device__ __forceinline__ float sum2(unsigned long long a)
{
    float lo, hi;
    asm("mov.b64 {%0, %1}, %2;" : "=f"(lo), "=f"(hi) : "l"(a));
    return lo + hi;
}
__device__ __forceinline__ float ex2_approx(float x)
{
    float r;
    asm("ex2.approx.f32 %0, %1;" : "=f"(r) : "f"(x));
    return r;
}

// ---------------------------------------------------------------------------
// Kernel 3: partial exp-sums of the NxN similarity matrix (R3 form).
// Grid (32, 32) x 128 threads -> 1024 blocks. Each thread carries TWO i-rows;
// j chunk = 256 rows in two 128-row shared phases. Diagonal only in ib==jb.
// ---------------------------------------------------------------------------
__global__ void __launch_bounds__(128) logits_kernel()
{
    __shared__ ulonglong2 sj[128 * 4];   // 128 j-rows * 16 floats = 8 KB
    int tid = threadIdx.x;
    int ib  = blockIdx.x;                // 0..31  -> i tile of 256
    int jb  = blockIdx.y;                // 0..31  -> j chunk of 256

    int i0 = ib * 256 + tid;
    int i1 = i0 + 128;

    ulonglong2 A0[4], A1[4];
    const ulonglong2* fs = (const ulonglong2*)g_fs;
#pragma unroll
    for (int q = 0; q < 4; q++) { A0[q] = fs[i0 * 4 + q]; A1[q] = fs[i1 * 4 + q]; }

    const ulonglong2* fu = (const ulonglong2*)g_fu;
    float sum0 = 0.f, sum1 = 0.f;
    int jch = jb * 256;
    bool diag = (ib == jb);

    for (int tph = 0; tph < 2; tph++) {
        int j0 = jch + tph * 128;
        __syncthreads();
#pragma unroll
        for (int q = 0; q < 4; q++) sj[tid * 4 + q] = fu[(j0 + tid) * 4 + q];
        __syncthreads();

        if (!diag) {
#pragma unroll 4
            for (int jj = 0; jj < 128; jj++) {
                ulonglong2 B0 = sj[jj * 4 + 0];
                ulonglong2 B1 = sj[jj * 4 + 1];
                ulonglong2 B2 = sj[jj * 4 + 2];
                ulonglong2 B3 = sj[jj * 4 + 3];

                unsigned long long acc0 = mul2(A0[0].x, B0.x);
                acc0 = fma2(A0[0].y, B0.y, acc0);
                acc0 = fma2(A0[1].x, B1.x, acc0);
                acc0 = fma2(A0[1].y, B1.y, acc0);
                acc0 = fma2(A0[2].x, B2.x, acc0);
                acc0 = fma2(A0[2].y, B2.y, acc0);
                acc0 = fma2(A0[3].x, B3.x, acc0);
                acc0 = fma2(A0[3].y, B3.y, acc0);

                unsigned long long acc1 = mul2(A1[0].x, B0.x);
                acc1 = fma2(A1[0].y, B0.y, acc1);
                acc1 = fma2(A1[1].x, B1.x, acc1);
                acc1 = fma2(A1[1].y, B1.y, acc1);
                acc1 = fma2(A1[2].x, B2.x, acc1);
                acc1 = fma2(A1[2].y, B2.y, acc1);
                acc1 = fma2(A1[3].x, B3.x, acc1);
                acc1 = fma2(A1[3].y, B3.y, acc1);

                sum0 += ex2_approx(sum2(acc0));
                sum1 += ex2_approx(sum2(acc1));
            }
        } else {
#pragma unroll 4
            for (int jj = 0; jj < 128; jj++) {
                ulonglong2 B0 = sj[jj * 4 + 0];
                ulonglong2 B1 = sj[jj * 4 + 1];
                ulonglong2 B2 = sj[jj * 4 + 2];
                ulonglong2 B3 = sj[jj * 4 + 3];

                unsigned long long acc0 = mul2(A0[0].x, B0.x);
                acc0 = fma2(A0[0].y, B0.y, acc0);
                acc0 = fma2(A0[1].x, B1.x, acc0);
                acc0 = fma2(A0[1].y, B1.y, acc0);
                acc0 = fma2(A0[2].x, B2.x, acc0);
                acc0 = fma2(A0[2].y, B2.y, acc0);
                acc0 = fma2(A0[3].x, B3.x, acc0);
                acc0 = fma2(A0[3].y, B3.y, acc0);

                unsigned long long acc1 = mul2(A1[0].x, B0.x);
                acc1 = fma2(A1[0].y, B0.y, acc1);
                acc1 = fma2(A1[1].x, B1.x, acc1);
                acc1 = fma2(A1[1].y, B1.y, acc1);
                acc1 = fma2(A1[2].x, B2.x, acc1);
                acc1 = fma2(A1[2].y, B2.y, acc1);
                acc1 = fma2(A1[3].x, B3.x, acc1);
                acc1 = fma2(A1[3].y, B3.y, acc1);

                float e0 = ex2_approx(sum2(acc0));
                float e1 = ex2_approx(sum2(acc1));
                int jg = j0 + jj;
                if (jg != i0) sum0 += e0;
                if (jg != i1) sum1 += e1;
            }
        }
    }

    g_partial[jb * N_ROWS + i0] = sum0;
    g_partial[jb * N_ROWS + i1] = sum1;
}

// ---------------------------------------------------------------------------
// Kernel 4a: per-row lse - pos, reduced within each of 32 blocks.
// ---------------------------------------------------------------------------
__global__ void __launch_bounds__(256) final_partial_kernel()
{
    __shared__ float red[256];
    int tid = threadIdx.x;
    int i   = blockIdx.x * 256 + tid;    // exactly 8192 threads, one row each

    float S = 0.f;
#pragma unroll
    for (int jb = 0; jb < NB_J; jb++) S += g_partial[jb * N_ROWS + i];

    int p = (i + 4096) & (N_ROWS - 1);
    const float4* a  = (const float4*)(g_fu + i * C_DIM);
    const float4* bb = (const float4*)(g_fu + p * C_DIM);
    float dot = 0.f;
#pragma unroll
    for (int q = 0; q < 4; q++) {
        float4 av = a[q], bv = bb[q];
        dot = fmaf(av.x, bv.x, dot);
        dot = fmaf(av.y, bv.y, dot);
        dot = fmaf(av.z, bv.z, dot);
        dot = fmaf(av.w, bv.w, dot);
    }

    red[tid] = logf(S) - 10.0f * dot;
    __syncthreads();
#pragma unroll
    for (int s = 128; s > 0; s >>= 1) {
        if (tid < s) red[tid] += red[tid + s];
        __syncthreads();
    }
    if (tid == 0) g_blocksum[blockIdx.x] = red[0];
}

// ---------------------------------------------------------------------------
// Kernel 4b: combine 32 block sums -> mean.
// ---------------------------------------------------------------------------
__global__ void __launch_bounds__(32) final_combine_kernel(float* __restrict__ out)
{
    int lane = threadIdx.x;
    float v = g_blocksum[lane];
#pragma unroll
    for (int s = 16; s > 0; s >>= 1) v += __shfl_xor_sync(0xffffffffu, v, s);
    if (lane == 0) out[0] = v * (1.0f / (float)N_ROWS);
}

// ---------------------------------------------------------------------------
extern "C" void kernel_launch(void* const* d_in, const int* in_sizes, int n_in,
                              void* d_out, int out_size)
{
    const float* p1 = (const float*)d_in[0];
    const float* p2 = (const float*)d_in[1];
    const float* w1 = (const float*)d_in[2];
    const float* b1 = (const float*)d_in[3];
    const float* w2 = (const float*)d_in[4];
    const float* b2 = (const float*)d_in[5];

    pool_kernel<<<4096, 256>>>(p1, p2);
    mlp_kernel<<<32, 256>>>(w1, b1, w2, b2);
    logits_kernel<<<dim3(32, 32), 128>>>();
    final_partial_kernel<<<32, 256>>>();
    final_combine_kernel<<<1, 32>>>((float*)d_out);
}

// round 6
// speedup vs baseline: 1.0796x; 1.0208x over previous
#include <cuda_runtime.h>
#include <cuda_bf16.h>
#include <cstdint>

// Problem constants
#define N_ROWS   8192      // 2 * B * S^3
#define C_DIM    16
#define NB_J     32        // j-chunks for logits kernel (chunk = 256 rows)
#define ESCALE   14.4269504088896340f   // 10 * log2(e): logits/T in log2 domain

// Scratch (device globals: no allocation allowed)
__device__ float g_mmA[N_ROWS * C_DIM];      // pool partial (dz 0..3), raw sums
__device__ float g_mmB[N_ROWS * C_DIM];      // pool partial (dz 4..7), raw sums
__device__ float g_fu[N_ROWS * C_DIM];       // normalized features
__device__ float g_fs[N_ROWS * C_DIM];       // normalized * ESCALE
__device__ float g_partial[NB_J * N_ROWS];   // partial exp-sums per j-chunk
__device__ float g_blocksum[32];             // per-block loss partials
__device__ unsigned int g_done = 0;          // last-block counter (self-resetting)

// ---------------------------------------------------------------------------
// Kernel 1: AdaptiveAvgPool3d(64->8), split over dz halves, streaming loads.
// ---------------------------------------------------------------------------
__global__ void __launch_bounds__(256) pool_kernel(const float* __restrict__ p1,
                                                   const float* __restrict__ p2)
{
    int bid  = blockIdx.x;           // 0..4095
    int t    = bid >> 11;            // tensor select
    int r    = bid & 2047;
    int b    = r >> 8;
    int c    = (r >> 4) & 15;
    int sd   = (r >> 1) & 7;
    int half = r & 1;

    const float* p = t ? p2 : p1;
    int tid    = threadIdx.x;
    int sh     = tid >> 5;           // warp id == sy
    int lane   = tid & 31;
    int rowsel = lane >> 4;
    int wid4   = lane & 15;

    const float4* base = (const float4*)(p + ((((b << 4) + c) * 64 + (sd << 3) + (half << 2)) << 12)
                                           + (sh << 3) * 64);

    float acc = 0.f;
#pragma unroll
    for (int dz = 0; dz < 4; dz++) {
#pragma unroll
        for (int hp = 0; hp < 4; hp++) {
            float4 v = __ldcs(base + dz * 1024 + (hp * 2 + rowsel) * 16 + wid4);
            acc += (v.x + v.y) + (v.z + v.w);
        }
    }
    acc += __shfl_xor_sync(0xffffffffu, acc, 1);
    acc += __shfl_xor_sync(0xffffffffu, acc, 16);

    if (((lane & 1) == 0) && lane < 16) {
        int sx  = lane >> 1;
        int row = t * 4096 + b * 512 + sd * 64 + sh * 8 + sx;
        float* dst = half ? g_mmB : g_mmA;
        dst[row * C_DIM + c] = acc;
    }
}

// ---------------------------------------------------------------------------
// Kernel 2: combine pool halves + project_head + F.normalize per row.
// ---------------------------------------------------------------------------
__global__ void __launch_bounds__(256) mlp_kernel(const float* __restrict__ w1,
                                                  const float* __restrict__ b1,
                                                  const float* __restrict__ w2,
                                                  const float* __restrict__ b2)
{
    __shared__ float sw1[256], sw2[256], sb1[16], sb2[16];
    int tid = threadIdx.x;
    sw1[tid] = w1[tid];
    sw2[tid] = w2[tid];
    if (tid < 16) { sb1[tid] = b1[tid]; sb2[tid] = b2[tid]; }
    __syncthreads();

    int row = blockIdx.x * 256 + tid;

    float x[16];
    const float4* ma4 = (const float4*)(g_mmA + row * C_DIM);
    const float4* mb4 = (const float4*)(g_mmB + row * C_DIM);
#pragma unroll
    for (int q = 0; q < 4; q++) {
        float4 va = ma4[q], vb = mb4[q];
        x[q * 4 + 0] = (va.x + vb.x) * (1.0f / 512.0f);
        x[q * 4 + 1] = (va.y + vb.y) * (1.0f / 512.0f);
        x[q * 4 + 2] = (va.z + vb.z) * (1.0f / 512.0f);
        x[q * 4 + 3] = (va.w + vb.w) * (1.0f / 512.0f);
    }

    float h[16];
#pragma unroll
    for (int k = 0; k < 16; k++) {
        float s = sb1[k];
#pragma unroll
        for (int cc = 0; cc < 16; cc++) s = fmaf(sw1[k * 16 + cc], x[cc], s);
        h[k] = fmaxf(s, 0.f);
    }

    float f[16];
    float nsq = 0.f;
#pragma unroll
    for (int k = 0; k < 16; k++) {
        float s = sb2[k];
#pragma unroll
        for (int cc = 0; cc < 16; cc++) s = fmaf(sw2[k * 16 + cc], h[cc], s);
        f[k] = s;
        nsq = fmaf(s, s, nsq);
    }
    float inv = 1.0f / fmaxf(sqrtf(nsq), 1e-12f);

    float4* fu4 = (float4*)(g_fu + row * C_DIM);
    float4* fs4 = (float4*)(g_fs + row * C_DIM);
#pragma unroll
    for (int q = 0; q < 4; q++) {
        float4 u;
        u.x = f[q * 4 + 0] * inv; u.y = f[q * 4 + 1] * inv;
        u.z = f[q * 4 + 2] * inv; u.w = f[q * 4 + 3] * inv;
        fu4[q] = u;
        float4 s2;
        s2.x = u.x * ESCALE; s2.y = u.y * ESCALE; s2.z = u.z * ESCALE; s2.w = u.w * ESCALE;
        fs4[q] = s2;
    }
}

// ---------------------------------------------------------------------------
// Packed f32x2 helpers
// ---------------------------------------------------------------------------
__device__ __forceinline__ unsigned long long fma2(unsigned long long a,
                                                   unsigned long long b,
                                                   unsigned long long c)
{
    unsigned long long d;
    asm("fma.rn.f32x2 %0, %1, %2, %3;" : "=l"(d) : "l"(a), "l"(b), "l"(c));
    return d;
}
__device__ __forceinline__ unsigned long long mul2(unsigned long long a,
                                                   unsigned long long b)
{
    unsigned long long d;
    asm("mul.rn.f32x2 %0, %1, %2;" : "=l"(d) : "l"(a), "l"(b));
    return d;
}
__device__ __forceinline__ unsigned long long add2(unsigned long long a,
                                                   unsigned long long b)
{
    unsigned long long d;
    asm("add.rn.f32x2 %0, %1, %2;" : "=l"(d) : "l"(a), "l"(b));
    return d;
}
__device__ __forceinline__ unsigned long long dup2(float a)
{
    unsigned long long d;
    asm("mov.b64 %0, {%1, %1};" : "=l"(d) : "f"(a));
    return d;
}
__device__ __forceinline__ unsigned long long pack2(float lo, float hi)
{
    unsigned long long d;
    asm("mov.b64 %0, {%1, %2};" : "=l"(d) : "f"(lo), "f"(hi));
    return d;
}
__device__ __forceinline__ void unpack2(float& lo, float& hi, unsigned long long a)
{
    asm("mov.b64 {%0, %1}, %2;" : "=f"(lo), "=f"(hi) : "l"(a));
}
__device__ __forceinline__ float ex2_approx(float x)
{
    float r;
    asm("ex2.approx.f32 %0, %1;" : "=f"(r) : "f"(x));
    return r;
}

// ---------------------------------------------------------------------------
// Kernel 3: partial exp-sums of the NxN similarity matrix, j-pair packed.
// Grid (32, 32) x 128 threads. Each thread: rows i0 = ib*256+tid, i1 = i0+128,
// with A duplicated into both f32x2 halves; shared j tile stores PAIRS of
// j-rows interleaved per k, so each FFMA2 chain produces two full dots
// (no horizontal reduction). 64 j-pairs per 128-row phase, 2 phases per chunk.
// ---------------------------------------------------------------------------
__global__ void __launch_bounds__(128) logits_kernel()
{
    // 64 j-pairs, 16 k-slots of float2, padded to 18 (144 B row: 16B-aligned,
    // and STS scatter is at worst 2-way bank conflicted)
    __shared__ float2 sjp[64 * 18];   // 9216 B

    int tid = threadIdx.x;
    int ib  = blockIdx.x;
    int jb  = blockIdx.y;

    int i0 = ib * 256 + tid;
    int i1 = i0 + 128;

    // duplicated A registers
    unsigned long long A0[16], A1[16];
    {
        const float4* f0 = (const float4*)(g_fs + i0 * C_DIM);
        const float4* f1 = (const float4*)(g_fs + i1 * C_DIM);
#pragma unroll
        for (int q = 0; q < 4; q++) {
            float4 v0 = f0[q], v1 = f1[q];
            A0[q * 4 + 0] = dup2(v0.x); A0[q * 4 + 1] = dup2(v0.y);
            A0[q * 4 + 2] = dup2(v0.z); A0[q * 4 + 3] = dup2(v0.w);
            A1[q * 4 + 0] = dup2(v1.x); A1[q * 4 + 1] = dup2(v1.y);
            A1[q * 4 + 2] = dup2(v1.z); A1[q * 4 + 3] = dup2(v1.w);
        }
    }

    unsigned long long S0 = 0ull, S1 = 0ull;  // packed row sums
    float d0 = 0.f, d1 = 0.f;                 // scalar sums (diag path)
    bool diag = (ib == jb);

    for (int tph = 0; tph < 2; tph++) {
        int j0base = jb * 256 + tph * 128;
        __syncthreads();
        {
            // thread tid loads fu row (j0base+tid), scatters into pair slot
            const float4* src = (const float4*)(g_fu + (j0base + tid) * C_DIM);
            float4 v0 = src[0], v1 = src[1], v2 = src[2], v3 = src[3];
            int pr = tid >> 1, sl = tid & 1;
            float* dst = (float*)&sjp[pr * 18];
            dst[0  + sl] = v0.x; dst[2  + sl] = v0.y; dst[4  + sl] = v0.z; dst[6  + sl] = v0.w;
            dst[8  + sl] = v1.x; dst[10 + sl] = v1.y; dst[12 + sl] = v1.z; dst[14 + sl] = v1.w;
            dst[16 + sl] = v2.x; dst[18 + sl] = v2.y; dst[20 + sl] = v2.z; dst[22 + sl] = v2.w;
            dst[24 + sl] = v3.x; dst[26 + sl] = v3.y; dst[28 + sl] = v3.z; dst[30 + sl] = v3.w;
        }
        __syncthreads();

        if (!diag) {
#pragma unroll 4
            for (int jp = 0; jp < 64; jp++) {
                const ulonglong2* bp = (const ulonglong2*)&sjp[jp * 18];
                ulonglong2 t0 = bp[0], t1 = bp[1], t2 = bp[2], t3 = bp[3];
                ulonglong2 t4 = bp[4], t5 = bp[5], t6 = bp[6], t7 = bp[7];

                unsigned long long acc0 = mul2(A0[0], t0.x);
                acc0 = fma2(A0[1],  t0.y, acc0);
                acc0 = fma2(A0[2],  t1.x, acc0);
                acc0 = fma2(A0[3],  t1.y, acc0);
                acc0 = fma2(A0[4],  t2.x, acc0);
                acc0 = fma2(A0[5],  t2.y, acc0);
                acc0 = fma2(A0[6],  t3.x, acc0);
                acc0 = fma2(A0[7],  t3.y, acc0);
                acc0 = fma2(A0[8],  t4.x, acc0);
                acc0 = fma2(A0[9],  t4.y, acc0);
                acc0 = fma2(A0[10], t5.x, acc0);
                acc0 = fma2(A0[11], t5.y, acc0);
                acc0 = fma2(A0[12], t6.x, acc0);
                acc0 = fma2(A0[13], t6.y, acc0);
                acc0 = fma2(A0[14], t7.x, acc0);
                acc0 = fma2(A0[15], t7.y, acc0);

                unsigned long long acc1 = mul2(A1[0], t0.x);
                acc1 = fma2(A1[1],  t0.y, acc1);
                acc1 = fma2(A1[2],  t1.x, acc1);
                acc1 = fma2(A1[3],  t1.y, acc1);
                acc1 = fma2(A1[4],  t2.x, acc1);
                acc1 = fma2(A1[5],  t2.y, acc1);
                acc1 = fma2(A1[6],  t3.x, acc1);
                acc1 = fma2(A1[7],  t3.y, acc1);
                acc1 = fma2(A1[8],  t4.x, acc1);
                acc1 = fma2(A1[9],  t4.y, acc1);
                acc1 = fma2(A1[10], t5.x, acc1);
                acc1 = fma2(A1[11], t5.y, acc1);
                acc1 = fma2(A1[12], t6.x, acc1);
                acc1 = fma2(A1[13], t6.y, acc1);
                acc1 = fma2(A1[14], t7.x, acc1);
                acc1 = fma2(A1[15], t7.y, acc1);

                float z00, z01, z10, z11;
                unpack2(z00, z01, acc0);
                unpack2(z10, z11, acc1);
                float e00 = ex2_approx(z00), e01 = ex2_approx(z01);
                float e10 = ex2_approx(z10), e11 = ex2_approx(z11);
                S0 = add2(S0, pack2(e00, e01));
                S1 = add2(S1, pack2(e10, e11));
            }
        } else {
#pragma unroll 4
            for (int jp = 0; jp < 64; jp++) {
                const ulonglong2* bp = (const ulonglong2*)&sjp[jp * 18];
                ulonglong2 t0 = bp[0], t1 = bp[1], t2 = bp[2], t3 = bp[3];
                ulonglong2 t4 = bp[4], t5 = bp[5], t6 = bp[6], t7 = bp[7];

                unsigned long long acc0 = mul2(A0[0], t0.x);
                acc0 = fma2(A0[1],  t0.y, acc0);
                acc0 = fma2(A0[2],  t1.x, acc0);
                acc0 = fma2(A0[3],  t1.y, acc0);
                acc0 = fma2(A0[4],  t2.x, acc0);
                acc0 = fma2(A0[5],  t2.y, acc0);
                acc0 = fma2(A0[6],  t3.x, acc0);
                acc0 = fma2(A0[7],  t3.y, acc0);
                acc0 = fma2(A0[8],  t4.x, acc0);
                acc0 = fma2(A0[9],  t4.y, acc0);
                acc0 = fma2(A0[10], t5.x, acc0);
                acc0 = fma2(A0[11], t5.y, acc0);
                acc0 = fma2(A0[12], t6.x, acc0);
                acc0 = fma2(A0[13], t6.y, acc0);
                acc0 = fma2(A0[14], t7.x, acc0);
                acc0 = fma2(A0[15], t7.y, acc0);

                unsigned long long acc1 = mul2(A1[0], t0.x);
                acc1 = fma2(A1[1],  t0.y, acc1);
                acc1 = fma2(A1[2],  t1.x, acc1);
                acc1 = fma2(A1[3],  t1.y, acc1);
                acc1 = fma2(A1[4],  t2.x, acc1);
                acc1 = fma2(A1[5],  t2.y, acc1);
                acc1 = fma2(A1[6],  t3.x, acc1);
                acc1 = fma2(A1[7],  t3.y, acc1);
                acc1 = fma2(A1[8],  t4.x, acc1);
                acc1 = fma2(A1[9],  t4.y, acc1);
                acc1 = fma2(A1[10], t5.x, acc1);
                acc1 = fma2(A1[11], t5.y, acc1);
                acc1 = fma2(A1[12], t6.x, acc1);
                acc1 = fma2(A1[13], t6.y, acc1);
                acc1 = fma2(A1[14], t7.x, acc1);
                acc1 = fma2(A1[15], t7.y, acc1);

                float z00, z01, z10, z11;
                unpack2(z00, z01, acc0);
                unpack2(z10, z11, acc1);
                float e00 = ex2_approx(z00), e01 = ex2_approx(z01);
                float e10 = ex2_approx(z10), e11 = ex2_approx(z11);

                int jg0 = j0base + jp * 2;
                int jg1 = jg0 + 1;
                if (jg0 != i0) d0 += e00;
                if (jg1 != i0) d0 += e01;
                if (jg0 != i1) d1 += e10;
                if (jg1 != i1) d1 += e11;
            }
        }
    }

    float lo, hi;
    unpack2(lo, hi, S0);
    g_partial[jb * N_ROWS + i0] = lo + hi + d0;
    unpack2(lo, hi, S1);
    g_partial[jb * N_ROWS + i1] = lo + hi + d1;
}

// ---------------------------------------------------------------------------
// Kernel 4: per-row lse - pos, block reduce; last block combines (deterministic:
// the combining block sums all 32 slots in fixed order) and resets the counter.
// ---------------------------------------------------------------------------
__global__ void __launch_bounds__(256) final_kernel(float* __restrict__ out)
{
    __shared__ float red[256];
    __shared__ bool is_last;
    int tid = threadIdx.x;
    int i   = blockIdx.x * 256 + tid;    // exactly 8192 threads, one row each

    float S = 0.f;
#pragma unroll
    for (int jb = 0; jb < NB_J; jb++) S += g_partial[jb * N_ROWS + i];

    int p = (i + 4096) & (N_ROWS - 1);
    const float4* a  = (const float4*)(g_fu + i * C_DIM);
    const float4* bb = (const float4*)(g_fu + p * C_DIM);
    float dot = 0.f;
#pragma unroll
    for (int q = 0; q < 4; q++) {
        float4 av = a[q], bv = bb[q];
        dot = fmaf(av.x, bv.x, dot);
        dot = fmaf(av.y, bv.y, dot);
        dot = fmaf(av.z, bv.z, dot);
        dot = fmaf(av.w, bv.w, dot);
    }

    red[tid] = logf(S) - 10.0f * dot;
    __syncthreads();
#pragma unroll
    for (int s = 128; s > 0; s >>= 1) {
        if (tid < s) red[tid] += red[tid + s];
        __syncthreads();
    }
    if (tid == 0) {
        g_blocksum[blockIdx.x] = red[0];
        __threadfence();
        unsigned int done = atomicAdd(&g_done, 1u);
        is_last = (done == 31u);
    }
    __syncthreads();

    if (is_last && tid < 32) {
        float v = g_blocksum[tid];
#pragma unroll
        for (int s = 16; s > 0; s >>= 1) v += __shfl_xor_sync(0xffffffffu, v, s);
        if (tid == 0) {
            out[0] = v * (1.0f / (float)N_ROWS);
            g_done = 0;   // reset for next graph replay
        }
    }
}

// ---------------------------------------------------------------------------
extern "C" void kernel_launch(void* const* d_in, const int* in_sizes, int n_in,
                              void* d_out, int out_size)
{
    const float* p1 = (const float*)d_in[0];
    const float* p2 = (const float*)d_in[1];
    const float* w1 = (const float*)d_in[2];
    const float* b1 = (const float*)d_in[3];
    const float* w2 = (const float*)d_in[4];
    const float* b2 = (const float*)d_in[5];

    pool_kernel<<<4096, 256>>>(p1, p2);
    mlp_kernel<<<32, 256>>>(w1, b1, w2, b2);
    logits_kernel<<<dim3(32, 32), 128>>>();
    final_kernel<<<32, 256>>>((float*)d_out);
}

// round 8
// speedup vs baseline: 1.3169x; 1.2198x over previous
#include <cuda_runtime.h>
#include <cuda_bf16.h>
#include <cstdint>

// Problem constants
#define N_ROWS   8192      // 2 * B * S^3
#define C_DIM    16
#define NB_J     64        // j-tiles of 128 rows
#define ESCALE   14.4269504088896340f   // 10 * log2(e): logits/T in log2 domain

// Scratch (device globals: no allocation allowed)
__device__ float g_mmA[N_ROWS * C_DIM];      // pool partial (dz 0..3), raw sums
__device__ float g_mmB[N_ROWS * C_DIM];      // pool partial (dz 4..7), raw sums
__device__ float g_fu[N_ROWS * C_DIM];       // normalized features (fp32, pos-pair dot)
__device__ __nv_bfloat16 g_fsb[N_ROWS * 32]; // per row: [0:16) hi, [16:32) lo of ESCALE*f
__device__ __nv_bfloat16 g_fub[N_ROWS * 32]; // per row: [0:16) hi, [16:32) lo of f
__device__ float g_partial[NB_J * N_ROWS];   // per-row partial exp-sums per j-tile
__device__ float g_blocksum[32];
__device__ unsigned int g_done = 0;

// ---------------------------------------------------------------------------
// Kernel 1: AdaptiveAvgPool3d(64->8), split over dz halves, streaming loads.
// ---------------------------------------------------------------------------
__global__ void __launch_bounds__(256) pool_kernel(const float* __restrict__ p1,
                                                   const float* __restrict__ p2)
{
    int bid  = blockIdx.x;           // 0..4095
    int t    = bid >> 11;
    int r    = bid & 2047;
    int b    = r >> 8;
    int c    = (r >> 4) & 15;
    int sd   = (r >> 1) & 7;
    int half = r & 1;

    const float* p = t ? p2 : p1;
    int tid    = threadIdx.x;
    int sh     = tid >> 5;
    int lane   = tid & 31;
    int rowsel = lane >> 4;
    int wid4   = lane & 15;

    const float4* base = (const float4*)(p + ((((b << 4) + c) * 64 + (sd << 3) + (half << 2)) << 12)
                                           + (sh << 3) * 64);

    float acc = 0.f;
#pragma unroll
    for (int dz = 0; dz < 4; dz++) {
#pragma unroll
        for (int hp = 0; hp < 4; hp++) {
            float4 v = __ldcs(base + dz * 1024 + (hp * 2 + rowsel) * 16 + wid4);
            acc += (v.x + v.y) + (v.z + v.w);
        }
    }
    acc += __shfl_xor_sync(0xffffffffu, acc, 1);
    acc += __shfl_xor_sync(0xffffffffu, acc, 16);

    if (((lane & 1) == 0) && lane < 16) {
        int sx  = lane >> 1;
        int row = t * 4096 + b * 512 + sd * 64 + sh * 8 + sx;
        float* dst = half ? g_mmB : g_mmA;
        dst[row * C_DIM + c] = acc;
    }
}

// ---------------------------------------------------------------------------
// Kernel 2: combine pool halves + project_head + F.normalize per row.
// Emits fp32 g_fu and split-bf16 (hi+lo) MMA operand arrays.
// ---------------------------------------------------------------------------
__global__ void __launch_bounds__(256) mlp_kernel(const float* __restrict__ w1,
                                                  const float* __restrict__ b1,
                                                  const float* __restrict__ w2,
                                                  const float* __restrict__ b2)
{
    __shared__ float sw1[256], sw2[256], sb1[16], sb2[16];
    int tid = threadIdx.x;
    sw1[tid] = w1[tid];
    sw2[tid] = w2[tid];
    if (tid < 16) { sb1[tid] = b1[tid]; sb2[tid] = b2[tid]; }
    __syncthreads();

    int row = blockIdx.x * 256 + tid;

    float x[16];
    const float4* ma4 = (const float4*)(g_mmA + row * C_DIM);
    const float4* mb4 = (const float4*)(g_mmB + row * C_DIM);
#pragma unroll
    for (int q = 0; q < 4; q++) {
        float4 va = ma4[q], vb = mb4[q];
        x[q * 4 + 0] = (va.x + vb.x) * (1.0f / 512.0f);
        x[q * 4 + 1] = (va.y + vb.y) * (1.0f / 512.0f);
        x[q * 4 + 2] = (va.z + vb.z) * (1.0f / 512.0f);
        x[q * 4 + 3] = (va.w + vb.w) * (1.0f / 512.0f);
    }

    float h[16];
#pragma unroll
    for (int k = 0; k < 16; k++) {
        float s = sb1[k];
#pragma unroll
        for (int cc = 0; cc < 16; cc++) s = fmaf(sw1[k * 16 + cc], x[cc], s);
        h[k] = fmaxf(s, 0.f);
    }

    float f[16];
    float nsq = 0.f;
#pragma unroll
    for (int k = 0; k < 16; k++) {
        float s = sb2[k];
#pragma unroll
        for (int cc = 0; cc < 16; cc++) s = fmaf(sw2[k * 16 + cc], h[cc], s);
        f[k] = s;
        nsq = fmaf(s, s, nsq);
    }
    float inv = 1.0f / fmaxf(sqrtf(nsq), 1e-12f);

    float4* fu4 = (float4*)(g_fu + row * C_DIM);
    __nv_bfloat16* fsb = g_fsb + row * 32;
    __nv_bfloat16* fub = g_fub + row * 32;
#pragma unroll
    for (int q = 0; q < 4; q++) {
        float u[4];
        u[0] = f[q * 4 + 0] * inv; u[1] = f[q * 4 + 1] * inv;
        u[2] = f[q * 4 + 2] * inv; u[3] = f[q * 4 + 3] * inv;
        float4 uu; uu.x = u[0]; uu.y = u[1]; uu.z = u[2]; uu.w = u[3];
        fu4[q] = uu;
#pragma unroll
        for (int e = 0; e < 4; e++) {
            int k = q * 4 + e;
            float s  = u[e] * ESCALE;
            __nv_bfloat16 sh = __float2bfloat16(s);
            fsb[k]      = sh;
            fsb[16 + k] = __float2bfloat16(s - __bfloat162float(sh));
            __nv_bfloat16 uh = __float2bfloat16(u[e]);
            fub[k]      = uh;
            fub[16 + k] = __float2bfloat16(u[e] - __bfloat162float(uh));
        }
    }
}

// ---------------------------------------------------------------------------
// Warp-MMA helpers (baseline PTX: mma.sync + ldmatrix, sm_80+)
// ---------------------------------------------------------------------------
static __device__ __forceinline__ float ex2_approx(float x)
{
    float r;
    asm("ex2.approx.f32 %0, %1;" : "=f"(r) : "f"(x));
    return r;
}
static __device__ __forceinline__ uint32_t smem_u32(const void* p)
{
    return (uint32_t)__cvta_generic_to_shared(p);
}
static __device__ __forceinline__ void ldsm_x4(uint32_t* f, uint32_t addr)
{
    asm volatile("ldmatrix.sync.aligned.m8n8.x4.shared.b16 {%0,%1,%2,%3}, [%4];"
                 : "=r"(f[0]), "=r"(f[1]), "=r"(f[2]), "=r"(f[3]) : "r"(addr));
}
static __device__ __forceinline__ void ldsm_x2(uint32_t* f, uint32_t addr)
{
    asm volatile("ldmatrix.sync.aligned.m8n8.x2.shared.b16 {%0,%1}, [%2];"
                 : "=r"(f[0]), "=r"(f[1]) : "r"(addr));
}
static __device__ __forceinline__ void mma_bf16(float* d, const uint32_t* a, const uint32_t* b)
{
    asm volatile("mma.sync.aligned.m16n8k16.row.col.f32.bf16.bf16.f32 "
                 "{%0,%1,%2,%3}, {%4,%5,%6,%7}, {%8,%9}, {%0,%1,%2,%3};"
                 : "+f"(d[0]), "+f"(d[1]), "+f"(d[2]), "+f"(d[3])
                 : "r"(a[0]), "r"(a[1]), "r"(a[2]), "r"(a[3]), "r"(b[0]), "r"(b[1]));
}

#define SROW 80   // smem row stride (bytes): 16B-aligned, conflict-free for ldmatrix

// ---------------------------------------------------------------------------
// Kernel 3: logits exp-sums via warp-level split-bf16 tensor-core MMA.
// Grid (64, 64) x 128 threads. Tile 128x128: Z = Fs[i-tile] @ Fu[j-tile]^T via
// 3 MMAs per (m,n) fragment (ah*bh + ah*bl + al*bh), fp32 accumulate.
// Warp w owns output rows [32w, 32w+32); epilogue fuses ex2 + row sums.
// ---------------------------------------------------------------------------
__global__ void __launch_bounds__(128) logits_mma_kernel()
{
    __shared__ __align__(16) unsigned char smA[128 * SROW];
    __shared__ __align__(16) unsigned char smB[128 * SROW];

    int tid = threadIdx.x;
    int w   = tid >> 5;
    int l   = tid & 31;
    int ib  = blockIdx.x;
    int jb  = blockIdx.y;

    // Stage one A row + one B row per thread (64 B each: 16 hi + 16 lo bf16)
    {
        const uint4* srcA = (const uint4*)(g_fsb + (ib * 128 + tid) * 32);
        const uint4* srcB = (const uint4*)(g_fub + (jb * 128 + tid) * 32);
#pragma unroll
        for (int q = 0; q < 4; q++) *(uint4*)(smA + tid * SROW + q * 16) = srcA[q];
#pragma unroll
        for (int q = 0; q < 4; q++) *(uint4*)(smB + tid * SROW + q * 16) = srcB[q];
    }
    __syncthreads();

    // A fragments for this warp's two 16-row m-tiles, hi and lo terms.
    // ldmatrix x4 lane mapping: row = (l&7) + ((l>>3)&1)*8, k-half = l>>4.
    uint32_t Ah[2][4], Al[2][4];
    {
        int r  = (l & 7) + ((l >> 3) & 1) * 8;
        int kh = l >> 4;
#pragma unroll
        for (int mt = 0; mt < 2; mt++) {
            uint32_t a = smem_u32(smA + (w * 32 + mt * 16 + r) * SROW + kh * 16);
            ldsm_x4(Ah[mt], a);
            ldsm_x4(Al[mt], a + 32);
        }
    }

    bool diag = (ib == jb);
    float P0 = 0.f, P1 = 0.f, P2 = 0.f, P3 = 0.f;   // rows g, g+8, 16+g, 24+g
    int g = l >> 2;

    // B fragment ldmatrix x2 lane mapping (lanes 0-15): n = l&7, k-half = (l>>3)&1
    int bn  = l & 7;
    int bkh = (l >> 3) & 1;

#pragma unroll 4
    for (int nt = 0; nt < 16; nt++) {
        uint32_t bh[2], bl[2];
        uint32_t ba = smem_u32(smB + (nt * 8 + bn) * SROW + bkh * 16);
        ldsm_x2(bh, ba);
        ldsm_x2(bl, ba + 32);

#pragma unroll
        for (int mt = 0; mt < 2; mt++) {
            float d[4] = {0.f, 0.f, 0.f, 0.f};
            mma_bf16(d, Ah[mt], bh);
            mma_bf16(d, Ah[mt], bl);
            mma_bf16(d, Al[mt], bh);

            float e0 = ex2_approx(d[0]);
            float e1 = ex2_approx(d[1]);
            float e2 = ex2_approx(d[2]);
            float e3 = ex2_approx(d[3]);

            if (diag) {
                // D frag: d0=(row g, col c0), d1=(g, c0+1), d2=(g+8, c0), d3=(g+8, c0+1)
                int col0 = jb * 128 + nt * 8 + (l & 3) * 2;
                int row0 = ib * 128 + w * 32 + mt * 16 + g;
                if (row0 == col0)         e0 = 0.f;
                if (row0 == col0 + 1)     e1 = 0.f;
                if (row0 + 8 == col0)     e2 = 0.f;
                if (row0 + 8 == col0 + 1) e3 = 0.f;
            }
            if (mt == 0) { P0 += e0 + e1; P1 += e2 + e3; }
            else         { P2 += e0 + e1; P3 += e2 + e3; }
        }
    }

    // Reduce across the 4 lanes of each quad (same row set)
    P0 += __shfl_xor_sync(0xffffffffu, P0, 1);
    P0 += __shfl_xor_sync(0xffffffffu, P0, 2);
    P1 += __shfl_xor_sync(0xffffffffu, P1, 1);
    P1 += __shfl_xor_sync(0xffffffffu, P1, 2);
    P2 += __shfl_xor_sync(0xffffffffu, P2, 1);
    P2 += __shfl_xor_sync(0xffffffffu, P2, 2);
    P3 += __shfl_xor_sync(0xffffffffu, P3, 1);
    P3 += __shfl_xor_sync(0xffffffffu, P3, 2);

    if ((l & 3) == 0) {
        int base = jb * N_ROWS + ib * 128 + w * 32;
        g_partial[base + g]      = P0;
        g_partial[base + 8 + g]  = P1;
        g_partial[base + 16 + g] = P2;
        g_partial[base + 24 + g] = P3;
    }
}

// ---------------------------------------------------------------------------
// Kernel 4: per-row lse - pos, block reduce; last block combines + resets.
// ---------------------------------------------------------------------------
__global__ void __launch_bounds__(256) final_kernel(float* __restrict__ out)
{
    __shared__ float red[256];
    __shared__ bool is_last;
    int tid = threadIdx.x;
    int i   = blockIdx.x * 256 + tid;

    float S = 0.f;
#pragma unroll
    for (int jb = 0; jb < NB_J; jb++) S += g_partial[jb * N_ROWS + i];

    int p = (i + 4096) & (N_ROWS - 1);
    const float4* a  = (const float4*)(g_fu + i * C_DIM);
    const float4* bb = (const float4*)(g_fu + p * C_DIM);
    float dot = 0.f;
#pragma unroll
    for (int q = 0; q < 4; q++) {
        float4 av = a[q], bv = bb[q];
        dot = fmaf(av.x, bv.x, dot);
        dot = fmaf(av.y, bv.y, dot);
        dot = fmaf(av.z, bv.z, dot);
        dot = fmaf(av.w, bv.w, dot);
    }

    red[tid] = logf(S) - 10.0f * dot;
    __syncthreads();
#pragma unroll
    for (int s = 128; s > 0; s >>= 1) {
        if (tid < s) red[tid] += red[tid + s];
        __syncthreads();
    }
    if (tid == 0) {
        g_blocksum[blockIdx.x] = red[0];
        __threadfence();
        unsigned int done = atomicAdd(&g_done, 1u);
        is_last = (done == 31u);
    }
    __syncthreads();

    if (is_last && tid < 32) {
        float v = g_blocksum[tid];
#pragma unroll
        for (int s = 16; s > 0; s >>= 1) v += __shfl_xor_sync(0xffffffffu, v, s);
        if (tid == 0) {
            out[0] = v * (1.0f / (float)N_ROWS);
            g_done = 0;
        }
    }
}

// ---------------------------------------------------------------------------
extern "C" void kernel_launch(void* const* d_in, const int* in_sizes, int n_in,
                              void* d_out, int out_size)
{
    const float* p1 = (const float*)d_in[0];
    const float* p2 = (const float*)d_in[1];
    const float* w1 = (const float*)d_in[2];
    const float* b1 = (const float*)d_in[3];
    const float* w2 = (const float*)d_in[4];
    const float* b2 = (const float*)d_in[5];

    pool_kernel<<<4096, 256>>>(p1, p2);
    mlp_kernel<<<32, 256>>>(w1, b1, w2, b2);
    logits_mma_kernel<<<dim3(64, 64), 128>>>();
    final_kernel<<<32, 256>>>((float*)d_out);
}

// round 9
// speedup vs baseline: 1.3312x; 1.0109x over previous
#include <cuda_runtime.h>
#include <cuda_bf16.h>
#include <cstdint>

// Problem constants
#define N_ROWS   8192      // 2 * B * S^3
#define C_DIM    16
#define NB_J     64        // j-tiles of 128 rows
#define ESCALE   14.4269504088896340f   // 10 * log2(e): logits/T in log2 domain

// Scratch (device globals: no allocation allowed)
__device__ float g_mmA[N_ROWS * C_DIM];      // pool partial (dz 0..3), raw sums
__device__ float g_mmB[N_ROWS * C_DIM];      // pool partial (dz 4..7), raw sums
__device__ float g_fu[N_ROWS * C_DIM];       // normalized features (fp32, pos-pair dot)
__device__ __nv_bfloat16 g_fsb[N_ROWS * 32]; // per row: [0:16) hi, [16:32) lo of ESCALE*f
__device__ __nv_bfloat16 g_fub[N_ROWS * 32]; // per row: [0:16) hi, [16:32) lo of f
__device__ float g_partial[N_ROWS * NB_J];   // ROW-MAJOR: row i's 64 slots contiguous
__device__ float g_blocksum[256];
__device__ unsigned int g_done = 0;

// ---------------------------------------------------------------------------
// Kernel 1: AdaptiveAvgPool3d(64->8), split over dz halves, streaming loads.
// ---------------------------------------------------------------------------
__global__ void __launch_bounds__(256) pool_kernel(const float* __restrict__ p1,
                                                   const float* __restrict__ p2)
{
    int bid  = blockIdx.x;           // 0..4095
    int t    = bid >> 11;
    int r    = bid & 2047;
    int b    = r >> 8;
    int c    = (r >> 4) & 15;
    int sd   = (r >> 1) & 7;
    int half = r & 1;

    const float* p = t ? p2 : p1;
    int tid    = threadIdx.x;
    int sh     = tid >> 5;
    int lane   = tid & 31;
    int rowsel = lane >> 4;
    int wid4   = lane & 15;

    const float4* base = (const float4*)(p + ((((b << 4) + c) * 64 + (sd << 3) + (half << 2)) << 12)
                                           + (sh << 3) * 64);

    float acc = 0.f;
#pragma unroll
    for (int dz = 0; dz < 4; dz++) {
#pragma unroll
        for (int hp = 0; hp < 4; hp++) {
            float4 v = __ldcs(base + dz * 1024 + (hp * 2 + rowsel) * 16 + wid4);
            acc += (v.x + v.y) + (v.z + v.w);
        }
    }
    acc += __shfl_xor_sync(0xffffffffu, acc, 1);
    acc += __shfl_xor_sync(0xffffffffu, acc, 16);

    if (((lane & 1) == 0) && lane < 16) {
        int sx  = lane >> 1;
        int row = t * 4096 + b * 512 + sd * 64 + sh * 8 + sx;
        float* dst = half ? g_mmB : g_mmA;
        dst[row * C_DIM + c] = acc;
    }
}

// ---------------------------------------------------------------------------
// Kernel 2: combine pool halves + project_head + F.normalize per row.
// Emits fp32 g_fu and split-bf16 (hi+lo) MMA operand arrays.
// ---------------------------------------------------------------------------
__global__ void __launch_bounds__(256) mlp_kernel(const float* __restrict__ w1,
                                                  const float* __restrict__ b1,
                                                  const float* __restrict__ w2,
                                                  const float* __restrict__ b2)
{
    __shared__ float sw1[256], sw2[256], sb1[16], sb2[16];
    int tid = threadIdx.x;
    sw1[tid] = w1[tid];
    sw2[tid] = w2[tid];
    if (tid < 16) { sb1[tid] = b1[tid]; sb2[tid] = b2[tid]; }
    __syncthreads();

    int row = blockIdx.x * 256 + tid;

    float x[16];
    const float4* ma4 = (const float4*)(g_mmA + row * C_DIM);
    const float4* mb4 = (const float4*)(g_mmB + row * C_DIM);
#pragma unroll
    for (int q = 0; q < 4; q++) {
        float4 va = ma4[q], vb = mb4[q];
        x[q * 4 + 0] = (va.x + vb.x) * (1.0f / 512.0f);
        x[q * 4 + 1] = (va.y + vb.y) * (1.0f / 512.0f);
        x[q * 4 + 2] = (va.z + vb.z) * (1.0f / 512.0f);
        x[q * 4 + 3] = (va.w + vb.w) * (1.0f / 512.0f);
    }

    float h[16];
#pragma unroll
    for (int k = 0; k < 16; k++) {
        float s = sb1[k];
#pragma unroll
        for (int cc = 0; cc < 16; cc++) s = fmaf(sw1[k * 16 + cc], x[cc], s);
        h[k] = fmaxf(s, 0.f);
    }

    float f[16];
    float nsq = 0.f;
#pragma unroll
    for (int k = 0; k < 16; k++) {
        float s = sb2[k];
#pragma unroll
        for (int cc = 0; cc < 16; cc++) s = fmaf(sw2[k * 16 + cc], h[cc], s);
        f[k] = s;
        nsq = fmaf(s, s, nsq);
    }
    float inv = 1.0f / fmaxf(sqrtf(nsq), 1e-12f);

    float4* fu4 = (float4*)(g_fu + row * C_DIM);
    __nv_bfloat16* fsb = g_fsb + row * 32;
    __nv_bfloat16* fub = g_fub + row * 32;
#pragma unroll
    for (int q = 0; q < 4; q++) {
        float u[4];
        u[0] = f[q * 4 + 0] * inv; u[1] = f[q * 4 + 1] * inv;
        u[2] = f[q * 4 + 2] * inv; u[3] = f[q * 4 + 3] * inv;
        float4 uu; uu.x = u[0]; uu.y = u[1]; uu.z = u[2]; uu.w = u[3];
        fu4[q] = uu;
#pragma unroll
        for (int e = 0; e < 4; e++) {
            int k = q * 4 + e;
            float s  = u[e] * ESCALE;
            __nv_bfloat16 sh = __float2bfloat16(s);
            fsb[k]      = sh;
            fsb[16 + k] = __float2bfloat16(s - __bfloat162float(sh));
            __nv_bfloat16 uh = __float2bfloat16(u[e]);
            fub[k]      = uh;
            fub[16 + k] = __float2bfloat16(u[e] - __bfloat162float(uh));
        }
    }
}

// ---------------------------------------------------------------------------
// Warp-MMA helpers (baseline PTX: mma.sync + ldmatrix, sm_80+)
// ---------------------------------------------------------------------------
static __device__ __forceinline__ float ex2_approx(float x)
{
    float r;
    asm("ex2.approx.f32 %0, %1;" : "=f"(r) : "f"(x));
    return r;
}
static __device__ __forceinline__ uint32_t smem_u32(const void* p)
{
    return (uint32_t)__cvta_generic_to_shared(p);
}
static __device__ __forceinline__ void ldsm_x4(uint32_t* f, uint32_t addr)
{
    asm volatile("ldmatrix.sync.aligned.m8n8.x4.shared.b16 {%0,%1,%2,%3}, [%4];"
                 : "=r"(f[0]), "=r"(f[1]), "=r"(f[2]), "=r"(f[3]) : "r"(addr));
}
static __device__ __forceinline__ void ldsm_x2(uint32_t* f, uint32_t addr)
{
    asm volatile("ldmatrix.sync.aligned.m8n8.x2.shared.b16 {%0,%1}, [%2];"
                 : "=r"(f[0]), "=r"(f[1]) : "r"(addr));
}
static __device__ __forceinline__ void mma_bf16(float* d, const uint32_t* a, const uint32_t* b)
{
    asm volatile("mma.sync.aligned.m16n8k16.row.col.f32.bf16.bf16.f32 "
                 "{%0,%1,%2,%3}, {%4,%5,%6,%7}, {%8,%9}, {%0,%1,%2,%3};"
                 : "+f"(d[0]), "+f"(d[1]), "+f"(d[2]), "+f"(d[3])
                 : "r"(a[0]), "r"(a[1]), "r"(a[2]), "r"(a[3]), "r"(b[0]), "r"(b[1]));
}

#define SROW 80   // smem row stride (bytes): 16B-aligned, conflict-free for ldmatrix

// ---------------------------------------------------------------------------
// Kernel 3: logits exp-sums via warp-level split-bf16 tensor-core MMA.
// Grid (64, 64) x 128 threads. Tile 128x128: Z = Fs[i-tile] @ Fu[j-tile]^T via
// 3 MMAs per (m,n) fragment (ah*bh + ah*bl + al*bh), fp32 accumulate.
// Warp w owns output rows [32w, 32w+32); epilogue fuses ex2 + row sums.
// Partial sums stored ROW-MAJOR: g_partial[row * 64 + jb].
// ---------------------------------------------------------------------------
__global__ void __launch_bounds__(128) logits_mma_kernel()
{
    __shared__ __align__(16) unsigned char smA[128 * SROW];
    __shared__ __align__(16) unsigned char smB[128 * SROW];

    int tid = threadIdx.x;
    int w   = tid >> 5;
    int l   = tid & 31;
    int ib  = blockIdx.x;
    int jb  = blockIdx.y;

    // Stage one A row + one B row per thread (64 B each: 16 hi + 16 lo bf16)
    {
        const uint4* srcA = (const uint4*)(g_fsb + (ib * 128 + tid) * 32);
        const uint4* srcB = (const uint4*)(g_fub + (jb * 128 + tid) * 32);
#pragma unroll
        for (int q = 0; q < 4; q++) *(uint4*)(smA + tid * SROW + q * 16) = srcA[q];
#pragma unroll
        for (int q = 0; q < 4; q++) *(uint4*)(smB + tid * SROW + q * 16) = srcB[q];
    }
    __syncthreads();

    // A fragments for this warp's two 16-row m-tiles, hi and lo terms.
    uint32_t Ah[2][4], Al[2][4];
    {
        int r  = (l & 7) + ((l >> 3) & 1) * 8;
        int kh = l >> 4;
#pragma unroll
        for (int mt = 0; mt < 2; mt++) {
            uint32_t a = smem_u32(smA + (w * 32 + mt * 16 + r) * SROW + kh * 16);
            ldsm_x4(Ah[mt], a);
            ldsm_x4(Al[mt], a + 32);
        }
    }

    bool diag = (ib == jb);
    float P0 = 0.f, P1 = 0.f, P2 = 0.f, P3 = 0.f;   // rows g, g+8, 16+g, 24+g
    int g = l >> 2;

    int bn  = l & 7;
    int bkh = (l >> 3) & 1;

#pragma unroll 4
    for (int nt = 0; nt < 16; nt++) {
        uint32_t bh[2], bl[2];
        uint32_t ba = smem_u32(smB + (nt * 8 + bn) * SROW + bkh * 16);
        ldsm_x2(bh, ba);
        ldsm_x2(bl, ba + 32);

#pragma unroll
        for (int mt = 0; mt < 2; mt++) {
            float d[4] = {0.f, 0.f, 0.f, 0.f};
            mma_bf16(d, Ah[mt], bh);
            mma_bf16(d, Ah[mt], bl);
            mma_bf16(d, Al[mt], bh);

            float e0 = ex2_approx(d[0]);
            float e1 = ex2_approx(d[1]);
            float e2 = ex2_approx(d[2]);
            float e3 = ex2_approx(d[3]);

            if (diag) {
                int col0 = jb * 128 + nt * 8 + (l & 3) * 2;
                int row0 = ib * 128 + w * 32 + mt * 16 + g;
                if (row0 == col0)         e0 = 0.f;
                if (row0 == col0 + 1)     e1 = 0.f;
                if (row0 + 8 == col0)     e2 = 0.f;
                if (row0 + 8 == col0 + 1) e3 = 0.f;
            }
            if (mt == 0) { P0 += e0 + e1; P1 += e2 + e3; }
            else         { P2 += e0 + e1; P3 += e2 + e3; }
        }
    }

    // Reduce across the 4 lanes of each quad (same row set)
    P0 += __shfl_xor_sync(0xffffffffu, P0, 1);
    P0 += __shfl_xor_sync(0xffffffffu, P0, 2);
    P1 += __shfl_xor_sync(0xffffffffu, P1, 1);
    P1 += __shfl_xor_sync(0xffffffffu, P1, 2);
    P2 += __shfl_xor_sync(0xffffffffu, P2, 1);
    P2 += __shfl_xor_sync(0xffffffffu, P2, 2);
    P3 += __shfl_xor_sync(0xffffffffu, P3, 1);
    P3 += __shfl_xor_sync(0xffffffffu, P3, 2);

    if ((l & 3) == 0) {
        int rowbase = ib * 128 + w * 32;
        g_partial[(rowbase + g)      * NB_J + jb] = P0;
        g_partial[(rowbase + 8 + g)  * NB_J + jb] = P1;
        g_partial[(rowbase + 16 + g) * NB_J + jb] = P2;
        g_partial[(rowbase + 24 + g) * NB_J + jb] = P3;
    }
}

// ---------------------------------------------------------------------------
// Kernel 4: per-row lse - pos. Grid 256 x 256 threads: 8 threads per row
// (each sums 8 contiguous slots), shfl-combine, block reduce, last-block
// combine (deterministic fixed-order reductions; counter self-resets).
// ---------------------------------------------------------------------------
__global__ void __launch_bounds__(256) final_kernel(float* __restrict__ out)
{
    __shared__ float red[32];
    __shared__ float wsum[8];
    __shared__ bool is_last;
    int tid  = threadIdx.x;
    int sub  = tid & 7;            // slot octant
    int r    = tid >> 3;           // row within block (0..31)
    int i    = blockIdx.x * 32 + r;

    // Sum 8 contiguous slots (32 B aligned pair of float4)
    const float4* pr = (const float4*)(g_partial + i * NB_J + sub * 8);
    float4 v0 = pr[0], v1 = pr[1];
    float S = ((v0.x + v0.y) + (v0.z + v0.w)) + ((v1.x + v1.y) + (v1.z + v1.w));

    // reduce across the 8 lanes of this row group (lanes contiguous in warp)
    S += __shfl_xor_sync(0xffffffffu, S, 1);
    S += __shfl_xor_sync(0xffffffffu, S, 2);
    S += __shfl_xor_sync(0xffffffffu, S, 4);

    float val = 0.f;
    if (sub == 0) {
        int p = (i + 4096) & (N_ROWS - 1);
        const float4* a  = (const float4*)(g_fu + i * C_DIM);
        const float4* bb = (const float4*)(g_fu + p * C_DIM);
        float dot = 0.f;
#pragma unroll
        for (int q = 0; q < 4; q++) {
            float4 av = a[q], bv = bb[q];
            dot = fmaf(av.x, bv.x, dot);
            dot = fmaf(av.y, bv.y, dot);
            dot = fmaf(av.z, bv.z, dot);
            dot = fmaf(av.w, bv.w, dot);
        }
        val = logf(S) - 10.0f * dot;
        red[r] = val;
    }
    __syncthreads();

    // block reduce 32 row values (warp 0)
    if (tid < 32) {
        float v = red[tid];
        v += __shfl_xor_sync(0xffffffffu, v, 16);
        v += __shfl_xor_sync(0xffffffffu, v, 8);
        v += __shfl_xor_sync(0xffffffffu, v, 4);
        v += __shfl_xor_sync(0xffffffffu, v, 2);
        v += __shfl_xor_sync(0xffffffffu, v, 1);
        if (tid == 0) {
            g_blocksum[blockIdx.x] = v;
            __threadfence();
            unsigned int done = atomicAdd(&g_done, 1u);
            is_last = (done == 255u);
        }
    }
    __syncthreads();

    if (is_last) {
        float v = g_blocksum[tid];   // 256 values, one per thread
        v += __shfl_xor_sync(0xffffffffu, v, 16);
        v += __shfl_xor_sync(0xffffffffu, v, 8);
        v += __shfl_xor_sync(0xffffffffu, v, 4);
        v += __shfl_xor_sync(0xffffffffu, v, 2);
        v += __shfl_xor_sync(0xffffffffu, v, 1);
        if ((tid & 31) == 0) wsum[tid >> 5] = v;
        __syncthreads();
        if (tid == 0) {
            float t = 0.f;
#pragma unroll
            for (int q = 0; q < 8; q++) t += wsum[q];
            out[0] = t * (1.0f / (float)N_ROWS);
            g_done = 0;
        }
    }
}

// ---------------------------------------------------------------------------
extern "C" void kernel_launch(void* const* d_in, const int* in_sizes, int n_in,
                              void* d_out, int out_size)
{
    const float* p1 = (const float*)d_in[0];
    const float* p2 = (const float*)d_in[1];
    const float* w1 = (const float*)d_in[2];
    const float* b1 = (const float*)d_in[3];
    const float* w2 = (const float*)d_in[4];
    const float* b2 = (const float*)d_in[5];

    pool_kernel<<<4096, 256>>>(p1, p2);
    mlp_kernel<<<32, 256>>>(w1, b1, w2, b2);
    logits_mma_kernel<<<dim3(64, 64), 128>>>();
    final_kernel<<<256, 256>>>((float*)d_out);
}

// round 10
// speedup vs baseline: 1.3647x; 1.0252x over previous
#include <cuda_runtime.h>
#include <cuda_bf16.h>
#include <cstdint>

// Problem constants
#define N_ROWS   8192      // 2 * B * S^3
#define C_DIM    16
#define ESCALE   14.4269504088896340f   // 10 * log2(e): logits/T in log2 domain

// Scratch (device globals: no allocation allowed)
__device__ float g_mmA[N_ROWS * C_DIM];      // pool partial (dz 0..3), raw sums
__device__ float g_mmB[N_ROWS * C_DIM];      // pool partial (dz 4..7), raw sums
__device__ float g_fu[N_ROWS * C_DIM];       // normalized features (fp32, pos-pair dot)
__device__ __nv_bfloat16 g_fsb[N_ROWS * 32]; // per row: [0:16) hi, [16:32) lo of ESCALE*f
__device__ __nv_bfloat16 g_fub[N_ROWS * 32]; // per row: [0:16) hi, [16:32) lo of f
__device__ float g_rowsum[N_ROWS];           // exp-sum per row (atomic accumulation)
__device__ float g_blocksum[32];
__device__ unsigned int g_done = 0;

// ---------------------------------------------------------------------------
// Kernel 1: AdaptiveAvgPool3d(64->8), split over dz halves, streaming loads.
// First 32 blocks also zero g_rowsum (completes before logits launch).
// ---------------------------------------------------------------------------
__global__ void __launch_bounds__(256) pool_kernel(const float* __restrict__ p1,
                                                   const float* __restrict__ p2)
{
    int bid  = blockIdx.x;           // 0..4095
    int tid  = threadIdx.x;
    if (bid < 32) g_rowsum[bid * 256 + tid] = 0.f;

    int t    = bid >> 11;
    int r    = bid & 2047;
    int b    = r >> 8;
    int c    = (r >> 4) & 15;
    int sd   = (r >> 1) & 7;
    int half = r & 1;

    const float* p = t ? p2 : p1;
    int sh     = tid >> 5;
    int lane   = tid & 31;
    int rowsel = lane >> 4;
    int wid4   = lane & 15;

    const float4* base = (const float4*)(p + ((((b << 4) + c) * 64 + (sd << 3) + (half << 2)) << 12)
                                           + (sh << 3) * 64);

    float acc = 0.f;
#pragma unroll
    for (int dz = 0; dz < 4; dz++) {
#pragma unroll
        for (int hp = 0; hp < 4; hp++) {
            float4 v = __ldcs(base + dz * 1024 + (hp * 2 + rowsel) * 16 + wid4);
            acc += (v.x + v.y) + (v.z + v.w);
        }
    }
    acc += __shfl_xor_sync(0xffffffffu, acc, 1);
    acc += __shfl_xor_sync(0xffffffffu, acc, 16);

    if (((lane & 1) == 0) && lane < 16) {
        int sx  = lane >> 1;
        int row = t * 4096 + b * 512 + sd * 64 + sh * 8 + sx;
        float* dst = half ? g_mmB : g_mmA;
        dst[row * C_DIM + c] = acc;
    }
}

// ---------------------------------------------------------------------------
// Kernel 2: combine pool halves + project_head + F.normalize per row.
// Emits fp32 g_fu and split-bf16 (hi+lo) MMA operand arrays.
// ---------------------------------------------------------------------------
__global__ void __launch_bounds__(256) mlp_kernel(const float* __restrict__ w1,
                                                  const float* __restrict__ b1,
                                                  const float* __restrict__ w2,
                                                  const float* __restrict__ b2)
{
    __shared__ float sw1[256], sw2[256], sb1[16], sb2[16];
    int tid = threadIdx.x;
    sw1[tid] = w1[tid];
    sw2[tid] = w2[tid];
    if (tid < 16) { sb1[tid] = b1[tid]; sb2[tid] = b2[tid]; }
    __syncthreads();

    int row = blockIdx.x * 256 + tid;

    float x[16];
    const float4* ma4 = (const float4*)(g_mmA + row * C_DIM);
    const float4* mb4 = (const float4*)(g_mmB + row * C_DIM);
#pragma unroll
    for (int q = 0; q < 4; q++) {
        float4 va = ma4[q], vb = mb4[q];
        x[q * 4 + 0] = (va.x + vb.x) * (1.0f / 512.0f);
        x[q * 4 + 1] = (va.y + vb.y) * (1.0f / 512.0f);
        x[q * 4 + 2] = (va.z + vb.z) * (1.0f / 512.0f);
        x[q * 4 + 3] = (va.w + vb.w) * (1.0f / 512.0f);
    }

    float h[16];
#pragma unroll
    for (int k = 0; k < 16; k++) {
        float s = sb1[k];
#pragma unroll
        for (int cc = 0; cc < 16; cc++) s = fmaf(sw1[k * 16 + cc], x[cc], s);
        h[k] = fmaxf(s, 0.f);
    }

    float f[16];
    float nsq = 0.f;
#pragma unroll
    for (int k = 0; k < 16; k++) {
        float s = sb2[k];
#pragma unroll
        for (int cc = 0; cc < 16; cc++) s = fmaf(sw2[k * 16 + cc], h[cc], s);
        f[k] = s;
        nsq = fmaf(s, s, nsq);
    }
    float inv = 1.0f / fmaxf(sqrtf(nsq), 1e-12f);

    float4* fu4 = (float4*)(g_fu + row * C_DIM);
    __nv_bfloat16* fsb = g_fsb + row * 32;
    __nv_bfloat16* fub = g_fub + row * 32;
#pragma unroll
    for (int q = 0; q < 4; q++) {
        float u[4];
        u[0] = f[q * 4 + 0] * inv; u[1] = f[q * 4 + 1] * inv;
        u[2] = f[q * 4 + 2] * inv; u[3] = f[q * 4 + 3] * inv;
        float4 uu; uu.x = u[0]; uu.y = u[1]; uu.z = u[2]; uu.w = u[3];
        fu4[q] = uu;
#pragma unroll
        for (int e = 0; e < 4; e++) {
            int k = q * 4 + e;
            float s  = u[e] * ESCALE;
            __nv_bfloat16 sh = __float2bfloat16(s);
            fsb[k]      = sh;
            fsb[16 + k] = __float2bfloat16(s - __bfloat162float(sh));
            __nv_bfloat16 uh = __float2bfloat16(u[e]);
            fub[k]      = uh;
            fub[16 + k] = __float2bfloat16(u[e] - __bfloat162float(uh));
        }
    }
}

// ---------------------------------------------------------------------------
// Warp-MMA helpers (baseline PTX: mma.sync + ldmatrix, sm_80+)
// ---------------------------------------------------------------------------
static __device__ __forceinline__ float ex2_approx(float x)
{
    float r;
    asm("ex2.approx.f32 %0, %1;" : "=f"(r) : "f"(x));
    return r;
}
static __device__ __forceinline__ uint32_t smem_u32(const void* p)
{
    return (uint32_t)__cvta_generic_to_shared(p);
}
static __device__ __forceinline__ void ldsm_x4(uint32_t* f, uint32_t addr)
{
    asm volatile("ldmatrix.sync.aligned.m8n8.x4.shared.b16 {%0,%1,%2,%3}, [%4];"
                 : "=r"(f[0]), "=r"(f[1]), "=r"(f[2]), "=r"(f[3]) : "r"(addr));
}
static __device__ __forceinline__ void ldsm_x2(uint32_t* f, uint32_t addr)
{
    asm volatile("ldmatrix.sync.aligned.m8n8.x2.shared.b16 {%0,%1}, [%2];"
                 : "=r"(f[0]), "=r"(f[1]) : "r"(addr));
}
static __device__ __forceinline__ void mma_bf16(float* d, const uint32_t* a, const uint32_t* b)
{
    asm volatile("mma.sync.aligned.m16n8k16.row.col.f32.bf16.bf16.f32 "
                 "{%0,%1,%2,%3}, {%4,%5,%6,%7}, {%8,%9}, {%0,%1,%2,%3};"
                 : "+f"(d[0]), "+f"(d[1]), "+f"(d[2]), "+f"(d[3])
                 : "r"(a[0]), "r"(a[1]), "r"(a[2]), "r"(a[3]), "r"(b[0]), "r"(b[1]));
}

#define SROW 80   // smem row stride (bytes): 16B-aligned, conflict-free for ldmatrix

// ---------------------------------------------------------------------------
// Kernel 3: logits exp-sums via symmetric split-bf16 tensor-core MMA.
// Grid (64, 64) x 128 threads; lower-triangle blocks (jb < ib) exit.
// Off-diagonal tiles are computed ONCE: each exp feeds the i-row sum and,
// via symmetry (z_ij = z_ji), the j-row sum through per-nt column reductions.
// All sums accumulate atomically into g_rowsum (FP ordering noise ~1e-7).
// ---------------------------------------------------------------------------
__global__ void __launch_bounds__(128) logits_mma_kernel()
{
    __shared__ __align__(16) unsigned char smA[128 * SROW];
    __shared__ __align__(16) unsigned char smB[128 * SROW];

    int ib  = blockIdx.x;
    int jb  = blockIdx.y;
    if (jb < ib) return;
    bool diag = (ib == jb);

    int tid = threadIdx.x;
    int w   = tid >> 5;
    int l   = tid & 31;

    // Stage one A row + one B row per thread (64 B each: 16 hi + 16 lo bf16)
    {
        const uint4* srcA = (const uint4*)(g_fsb + (ib * 128 + tid) * 32);
        const uint4* srcB = (const uint4*)(g_fub + (jb * 128 + tid) * 32);
#pragma unroll
        for (int q = 0; q < 4; q++) *(uint4*)(smA + tid * SROW + q * 16) = srcA[q];
#pragma unroll
        for (int q = 0; q < 4; q++) *(uint4*)(smB + tid * SROW + q * 16) = srcB[q];
    }
    __syncthreads();

    // A fragments for this warp's two 16-row m-tiles, hi and lo terms.
    uint32_t Ah[2][4], Al[2][4];
    {
        int r  = (l & 7) + ((l >> 3) & 1) * 8;
        int kh = l >> 4;
#pragma unroll
        for (int mt = 0; mt < 2; mt++) {
            uint32_t a = smem_u32(smA + (w * 32 + mt * 16 + r) * SROW + kh * 16);
            ldsm_x4(Ah[mt], a);
            ldsm_x4(Al[mt], a + 32);
        }
    }

    float P0 = 0.f, P1 = 0.f, P2 = 0.f, P3 = 0.f;   // rows g, g+8, 16+g, 24+g
    int g = l >> 2;

    int bn  = l & 7;
    int bkh = (l >> 3) & 1;

#pragma unroll 2
    for (int nt = 0; nt < 16; nt++) {
        uint32_t bh[2], bl[2];
        uint32_t ba = smem_u32(smB + (nt * 8 + bn) * SROW + bkh * 16);
        ldsm_x2(bh, ba);
        ldsm_x2(bl, ba + 32);

        float ca0 = 0.f, ca1 = 0.f;   // column sums for cols c0, c0+1 (this warp's 32 rows)

#pragma unroll
        for (int mt = 0; mt < 2; mt++) {
            float d[4] = {0.f, 0.f, 0.f, 0.f};
            mma_bf16(d, Ah[mt], bh);
            mma_bf16(d, Ah[mt], bl);
            mma_bf16(d, Al[mt], bh);

            float e0 = ex2_approx(d[0]);
            float e1 = ex2_approx(d[1]);
            float e2 = ex2_approx(d[2]);
            float e3 = ex2_approx(d[3]);

            if (diag) {
                int col0 = jb * 128 + nt * 8 + (l & 3) * 2;
                int row0 = ib * 128 + w * 32 + mt * 16 + g;
                if (row0 == col0)         e0 = 0.f;
                if (row0 == col0 + 1)     e1 = 0.f;
                if (row0 + 8 == col0)     e2 = 0.f;
                if (row0 + 8 == col0 + 1) e3 = 0.f;
            }
            if (mt == 0) { P0 += e0 + e1; P1 += e2 + e3; }
            else         { P2 += e0 + e1; P3 += e2 + e3; }

            ca0 += e0 + e2;
            ca1 += e1 + e3;
        }

        if (!diag) {
            // reduce column sums over the 8 g-groups (lane bits 2,3,4)
            ca0 += __shfl_xor_sync(0xffffffffu, ca0, 4);
            ca0 += __shfl_xor_sync(0xffffffffu, ca0, 8);
            ca0 += __shfl_xor_sync(0xffffffffu, ca0, 16);
            ca1 += __shfl_xor_sync(0xffffffffu, ca1, 4);
            ca1 += __shfl_xor_sync(0xffffffffu, ca1, 8);
            ca1 += __shfl_xor_sync(0xffffffffu, ca1, 16);
            if (l < 4) {
                int colbase = jb * 128 + nt * 8 + l * 2;
                atomicAdd(&g_rowsum[colbase],     ca0);
                atomicAdd(&g_rowsum[colbase + 1], ca1);
            }
        }
    }

    // Reduce row sums across the 4 lanes of each quad, accumulate atomically
    P0 += __shfl_xor_sync(0xffffffffu, P0, 1);
    P0 += __shfl_xor_sync(0xffffffffu, P0, 2);
    P1 += __shfl_xor_sync(0xffffffffu, P1, 1);
    P1 += __shfl_xor_sync(0xffffffffu, P1, 2);
    P2 += __shfl_xor_sync(0xffffffffu, P2, 1);
    P2 += __shfl_xor_sync(0xffffffffu, P2, 2);
    P3 += __shfl_xor_sync(0xffffffffu, P3, 1);
    P3 += __shfl_xor_sync(0xffffffffu, P3, 2);

    if ((l & 3) == 0) {
        int rowbase = ib * 128 + w * 32;
        atomicAdd(&g_rowsum[rowbase + g],      P0);
        atomicAdd(&g_rowsum[rowbase + 8 + g],  P1);
        atomicAdd(&g_rowsum[rowbase + 16 + g], P2);
        atomicAdd(&g_rowsum[rowbase + 24 + g], P3);
    }
}

// ---------------------------------------------------------------------------
// Kernel 4: per-row loss = log(rowsum) - pos; two-level deterministic-order
// reduction with last-block combine (counter self-resets for graph replay).
// ---------------------------------------------------------------------------
__global__ void __launch_bounds__(256) final_kernel(float* __restrict__ out)
{
    __shared__ float red[8];
    __shared__ bool is_last;
    int tid = threadIdx.x;
    int i   = blockIdx.x * 256 + tid;

    float S = g_rowsum[i];

    int p = (i + 4096) & (N_ROWS - 1);
    const float4* a  = (const float4*)(g_fu + i * C_DIM);
    const float4* bb = (const float4*)(g_fu + p * C_DIM);
    float dot = 0.f;
#pragma unroll
    for (int q = 0; q < 4; q++) {
        float4 av = a[q], bv = bb[q];
        dot = fmaf(av.x, bv.x, dot);
        dot = fmaf(av.y, bv.y, dot);
        dot = fmaf(av.z, bv.z, dot);
        dot = fmaf(av.w, bv.w, dot);
    }

    float v = logf(S) - 10.0f * dot;
    v += __shfl_xor_sync(0xffffffffu, v, 16);
    v += __shfl_xor_sync(0xffffffffu, v, 8);
    v += __shfl_xor_sync(0xffffffffu, v, 4);
    v += __shfl_xor_sync(0xffffffffu, v, 2);
    v += __shfl_xor_sync(0xffffffffu, v, 1);
    if ((tid & 31) == 0) red[tid >> 5] = v;
    __syncthreads();

    if (tid == 0) {
        float t = 0.f;
#pragma unroll
        for (int q = 0; q < 8; q++) t += red[q];
        g_blocksum[blockIdx.x] = t;
        __threadfence();
        unsigned int done = atomicAdd(&g_done, 1u);
        is_last = (done == 31u);
    }
    __syncthreads();

    if (is_last && tid < 32) {
        float u = g_blocksum[tid];
#pragma unroll
        for (int s = 16; s > 0; s >>= 1) u += __shfl_xor_sync(0xffffffffu, u, s);
        if (tid == 0) {
            out[0] = u * (1.0f / (float)N_ROWS);
            g_done = 0;
        }
    }
}

// ---------------------------------------------------------------------------
extern "C" void kernel_launch(void* const* d_in, const int* in_sizes, int n_in,
                              void* d_out, int out_size)
{
    const float* p1 = (const float*)d_in[0];
    const float* p2 = (const float*)d_in[1];
    const float* w1 = (const float*)d_in[2];
    const float* b1 = (const float*)d_in[3];
    const float* w2 = (const float*)d_in[4];
    const float* b2 = (const float*)d_in[5];

    pool_kernel<<<4096, 256>>>(p1, p2);
    mlp_kernel<<<32, 256>>>(w1, b1, w2, b2);
    logits_mma_kernel<<<dim3(64, 64), 128>>>();
    final_kernel<<<32, 256>>>((float*)d_out);
}